// round 6
// baseline (speedup 1.0000x reference)
#include <cuda_runtime.h>
#include <cuda_fp16.h>
#include <cstdint>

#define BATCH 8
#define CCH   48
#define NPIX  4096
#define NB    32768
#define KNN   9
#define NCAND 12            // per-slice top-k kept (4 slices/row)
#define ROWSTRIDE 120       // halves per smem row (96 data + 24 pad) = 240B

// ---------------- device scratch ----------------
__device__ float4   g_xn[NB * 12];     // normalized features fp32 (exact rerank)
__device__ float4   g_nodes[NB * 12];  // raw features (k5)
__device__ float    g_sq[NB];          // sum(xn^2)
__device__ uint32_t g_h16[NB * 48];    // per node: 24 half2 of hi | 24 half2 of lo (192B)
__device__ float    g_candd[NB * 4 * NCAND];
__device__ int      g_candi[NB * 4 * NCAND];
__device__ int      g_knn[NB * KNN];
__device__ int      g_deg[NB];

// ---------------- helpers ----------------
__device__ __forceinline__ uint32_t smem_u32(const void* p) {
    uint32_t a;
    asm("{ .reg .u64 t; cvta.to.shared.u64 t, %1; cvt.u32.u64 %0, t; }" : "=r"(a) : "l"(p));
    return a;
}
__device__ __forceinline__ void cp16(uint32_t dst, const void* src) {
    asm volatile("cp.async.cg.shared.global [%0], [%1], 16;" :: "r"(dst), "l"(src));
}
__device__ __forceinline__ void cp4(uint32_t dst, const void* src) {
    asm volatile("cp.async.ca.shared.global [%0], [%1], 4;" :: "r"(dst), "l"(src));
}
__device__ __forceinline__ void cp_commit() { asm volatile("cp.async.commit_group;"); }
template <int N> __device__ __forceinline__ void cp_wait() {
    asm volatile("cp.async.wait_group %0;" :: "n"(N));
}
__device__ __forceinline__ void ldsm4(uint32_t* R, uint32_t addr) {
    asm volatile("ldmatrix.sync.aligned.m8n8.x4.shared.b16 {%0,%1,%2,%3}, [%4];"
                 : "=r"(R[0]), "=r"(R[1]), "=r"(R[2]), "=r"(R[3]) : "r"(addr));
}
__device__ __forceinline__ void mma16816(float* C, const uint32_t* A, uint32_t b0, uint32_t b1) {
    asm volatile("mma.sync.aligned.m16n8k16.row.col.f32.f16.f16.f32 "
                 "{%0,%1,%2,%3}, {%4,%5,%6,%7}, {%8,%9}, {%0,%1,%2,%3};"
                 : "+f"(C[0]), "+f"(C[1]), "+f"(C[2]), "+f"(C[3])
                 : "r"(A[0]), "r"(A[1]), "r"(A[2]), "r"(A[3]), "r"(b0), "r"(b1));
}
// branchless sorted insert into 12-slot per-thread smem list; updates threshold
__device__ __forceinline__ void sel_insert(uint32_t base, float d, int idx, float& thr) {
    float cd = d; int ci = idx;
    #pragma unroll
    for (int k = 0; k < NCAND; k++) {
        uint32_t du, iu;
        asm volatile("ld.shared.v2.b32 {%0,%1}, [%2];" : "=r"(du), "=r"(iu)
                     : "r"(base + k * 8));
        float od = __uint_as_float(du); int oi = (int)iu;
        const bool sw = cd < od;
        float nd = sw ? cd : od; int ni = sw ? ci : oi;
        asm volatile("st.shared.v2.b32 [%0], {%1,%2};"
                     :: "r"(base + k * 8), "r"(__float_as_uint(nd)), "r"(ni) : "memory");
        cd = sw ? od : cd; ci = sw ? oi : ci;
        if (k == NCAND - 1) thr = nd;
    }
}

// ---------------- k2 smem layout (bytes) ----------------
#define OFF_A    0
#define OFF_B    30720                     // 2 x 30720
#define OFF_SQS  92160                     // 2 x 512
#define OFF_SEL  93184                     // 256 thr x 2 rows x 12 pairs x 8B
#define SMEM_K2  142336

// ======================================================================
// K1: transpose+normalize; emit xn (fp32, exact), nodes, sq, fp16 hi/lo.
// ======================================================================
__global__ __launch_bounds__(128) void k1_normalize(const float* __restrict__ x) {
    __shared__ float s[128 * 49];
    __shared__ float s_mn[128];
    __shared__ float s_rmn[128];
    const int tid  = threadIdx.x;
    const int n0g  = blockIdx.x * 128;
    const int b    = n0g >> 12;
    const int nloc = n0g & (NPIX - 1);

    const float* xb = x + (size_t)b * CCH * NPIX + nloc;
    #pragma unroll
    for (int c = 0; c < CCH; c++)
        s[tid * 49 + c] = xb[(size_t)c * NPIX + tid];

    float ss = 0.f;
    #pragma unroll
    for (int c = 0; c < CCH; c++) { float v = s[tid * 49 + c]; ss += v * v; }
    float mn = fmaxf(sqrtf(ss), 1e-12f);
    s_mn[tid]  = mn;
    s_rmn[tid] = 1.0f / mn;
    float sqv = 0.f;
    #pragma unroll
    for (int c = 0; c < CCH; c++) { float v = s[tid * 49 + c] / mn; sqv += v * v; }
    g_sq[n0g + tid]  = sqv;
    g_deg[n0g + tid] = 0;
    __syncthreads();

    float* nodes_f = (float*)g_nodes;
    float* xn_f    = (float*)g_xn;
    #pragma unroll
    for (int it = 0; it < 48; it++) {
        int idx = it * 128 + tid;
        int q = idx / 48, rr = idx - q * 48;
        float v = s[q * 49 + rr];
        nodes_f[(size_t)n0g * 48 + idx] = v;
        xn_f[(size_t)n0g * 48 + idx]    = v / s_mn[q];
    }
    // fp16 split, approx path only (rmn multiply OK)
    #pragma unroll
    for (int it = 0; it < 48; it++) {
        int idx = it * 128 + tid;            // 128 nodes x 48 u32 slots
        int q = idx / 48, c = idx - q * 48;  // node q, slot c
        int ch = (c < 24) ? c * 2 : (c - 24) * 2;
        float rm = s_rmn[q];
        float v0 = s[q * 49 + ch]     * rm;
        float v1 = s[q * 49 + ch + 1] * rm;
        __half h0 = __float2half_rn(v0);
        __half h1 = __float2half_rn(v1);
        __half2 outp;
        if (c < 24) outp = __halves2half2(h0, h1);
        else        outp = __halves2half2(__float2half_rn(v0 - __half2float(h0)),
                                          __float2half_rn(v1 - __half2float(h1)));
        g_h16[(size_t)(n0g + q) * 48 + c] = *(uint32_t*)&outp;
    }
}

// ======================================================================
// K2: Gram via mma.sync fp16-split (K=144 logical) + fragment-native
//     streaming per-slice top-12 selection.
// ======================================================================
__global__ __launch_bounds__(256, 1) void k2_knn() {
    extern __shared__ __align__(16) char smem[];
    const uint32_t sb = smem_u32(smem);
    const int tid  = threadIdx.x;
    const int wid  = tid >> 5;
    const int lane = tid & 31;
    const int g    = lane >> 2;
    const int tig  = lane & 3;
    const int b    = blockIdx.x >> 5;
    const int rt   = blockIdx.x & 31;
    const int rowbase = b * NPIX + rt * 128;

    // per-thread selection lists (smem): [rowA 12 pairs][rowB 12 pairs]
    const uint32_t selA = sb + OFF_SEL + tid * 192;
    const uint32_t selB = selA + 96;
    #pragma unroll
    for (int k = 0; k < NCAND; k++) {
        asm volatile("st.shared.v2.b32 [%0], {%1,%2};"
                     :: "r"(selA + k * 8), "r"(0x7f800000u), "r"(0x7fffffffu) : "memory");
        asm volatile("st.shared.v2.b32 [%0], {%1,%2};"
                     :: "r"(selB + k * 8), "r"(0x7f800000u), "r"(0x7fffffffu) : "memory");
    }
    float thrA = __int_as_float(0x7f800000);
    float thrB = __int_as_float(0x7f800000);

    // ldmatrix per-lane base addresses
    const int arow = ((lane >> 3) & 1) * 8 + (lane & 7);
    const int akof = ((lane >> 4) & 1) * 8;
    const uint32_t aBase = sb + OFF_A + (uint32_t)(wid * 16 + arow) * 240 + akof * 2;
    const int brow = ((lane >> 4) & 1) * 8 + (lane & 7);
    const int bkof = ((lane >> 3) & 1) * 8;
    const uint32_t bBase = sb + OFF_B + (uint32_t)brow * 240 + bkof * 2;

    // G0: A tile + B tile 0 + sqs0
    {
        const char* hsrc = (const char*)g_h16;
        #pragma unroll
        for (int i = 0; i < 6; i++) {
            int lin = tid + i * 256;                  // 1536 chunks of 16B
            int row = lin / 12, c = lin - row * 12;
            cp16(sb + OFF_A + row * 240 + c * 16,
                 hsrc + (size_t)(rowbase + row) * 192 + c * 16);
            cp16(sb + OFF_B + row * 240 + c * 16,
                 hsrc + (size_t)(b * NPIX + row) * 192 + c * 16);
        }
        if (tid < 128) cp4(sb + OFF_SQS + tid * 4, g_sq + b * NPIX + tid);
        cp_commit();
    }

    #pragma unroll 1
    for (int t = 0; t < 32; t++) {
        const int buf = t & 1;
        cp_wait<0>();
        __syncthreads();

        if (t < 31) {
            const int cb = b * NPIX + (t + 1) * 128;
            const char* hsrc = (const char*)g_h16;
            const uint32_t dstB = sb + OFF_B + (buf ^ 1) * 30720;
            #pragma unroll
            for (int i = 0; i < 6; i++) {
                int lin = tid + i * 256;
                int row = lin / 12, c = lin - row * 12;
                cp16(dstB + row * 240 + c * 16,
                     hsrc + (size_t)(cb + row) * 192 + c * 16);
            }
            if (tid < 128) cp4(sb + OFF_SQS + (buf ^ 1) * 512 + tid * 4, g_sq + cb + tid);
            cp_commit();
        }

        // ---- GEMM: 9 k16 chunks (ah*bh, ah*bl, al*bh), 16 n8 blocks ----
        float C[64];
        #pragma unroll
        for (int i = 0; i < 64; i++) C[i] = 0.f;
        const uint32_t bBuf = bBase + buf * 30720;
        #pragma unroll
        for (int c9 = 0; c9 < 9; c9++) {
            const int seg = c9 / 3, kc = c9 - seg * 3;
            const int ac = (seg < 2 ? 0 : 48) + kc * 16;
            const int bc = (seg == 1 ? 48 : 0) + kc * 16;
            uint32_t a[4];
            ldsm4(a, aBase + ac * 2);
            #pragma unroll
            for (int np = 0; np < 8; np++) {
                uint32_t bb[4];
                ldsm4(bb, bBuf + np * 3840 + bc * 2);
                mma16816(C + np * 8,     a, bb[0], bb[1]);
                mma16816(C + np * 8 + 4, a, bb[2], bb[3]);
            }
        }

        // ---- epilogue: d = sq[j] - 2*dot; per-slice top-12 ----
        const int colbase = b * NPIX + t * 128;
        #pragma unroll
        for (int nb = 0; nb < 16; nb++) {
            const int c0 = nb * 8 + tig * 2;
            const float2 sq2 = *(const float2*)(smem + OFF_SQS + buf * 512 + c0 * 4);
            const int gc = colbase + c0;
            const float dA0 = fmaf(-2.f, C[nb * 4 + 0], sq2.x);
            const float dA1 = fmaf(-2.f, C[nb * 4 + 1], sq2.y);
            const float dB0 = fmaf(-2.f, C[nb * 4 + 2], sq2.x);
            const float dB1 = fmaf(-2.f, C[nb * 4 + 3], sq2.y);
            if (dA0 < thrA) sel_insert(selA, dA0, gc,     thrA);
            if (dA1 < thrA) sel_insert(selA, dA1, gc + 1, thrA);
            if (dB0 < thrB) sel_insert(selB, dB0, gc,     thrB);
            if (dB1 < thrB) sel_insert(selB, dB1, gc + 1, thrB);
        }
    }

    // ---- writeout: per-thread lists -> g_cand ----
    const int nodeA = rowbase + wid * 16 + g;
    const int nodeB = nodeA + 8;
    #pragma unroll
    for (int k = 0; k < NCAND; k++) {
        uint32_t du, iu;
        asm volatile("ld.shared.v2.b32 {%0,%1}, [%2];" : "=r"(du), "=r"(iu) : "r"(selA + k * 8));
        g_candd[(size_t)(nodeA * 4 + tig) * NCAND + k] = __uint_as_float(du);
        g_candi[(size_t)(nodeA * 4 + tig) * NCAND + k] = (int)iu;
        asm volatile("ld.shared.v2.b32 {%0,%1}, [%2];" : "=r"(du), "=r"(iu) : "r"(selB + k * 8));
        g_candd[(size_t)(nodeB * 4 + tig) * NCAND + k] = __uint_as_float(du);
        g_candi[(size_t)(nodeB * 4 + tig) * NCAND + k] = (int)iu;
    }
}

// ======================================================================
// K3: approx-rank 48 slice candidates -> top-12 -> exact fp32 rerank ->
//     g_knn + degrees.  One 64-thread block per row.
// ======================================================================
__global__ __launch_bounds__(64) void k3_rerank() {
    const int row = blockIdx.x;
    const int t = threadIdx.x;
    __shared__ float s_row[48];
    __shared__ float s_d[48];
    __shared__ int   s_i[48];
    __shared__ float s_ed[12];
    __shared__ int   s_ei[12];

    if (t < 12) ((float4*)s_row)[t] = g_xn[(size_t)row * 12 + t];
    float d = 0.f; int idx = 0;
    if (t < 48) {
        d   = g_candd[(size_t)row * 48 + t];
        idx = g_candi[(size_t)row * 48 + t];
        s_d[t] = d; s_i[t] = idx;
    }
    __syncthreads();

    if (t < 48) {
        int rank = 0;
        #pragma unroll 8
        for (int o = 0; o < 48; o++) {
            float od = s_d[o]; int oi = s_i[o];
            rank += (od < d) || (od == d && oi < idx);
        }
        if (rank < 12) {
            const float4* cv = g_xn + (size_t)idx * 12;
            float acc = 0.f;
            #pragma unroll
            for (int q = 0; q < 12; q++) {
                float4 v = cv[q];
                acc += s_row[4 * q + 0] * v.x + s_row[4 * q + 1] * v.y
                     + s_row[4 * q + 2] * v.z + s_row[4 * q + 3] * v.w;
            }
            s_ed[rank] = fmaf(-2.f, acc, g_sq[idx]);
            s_ei[rank] = idx;
        }
    }
    __syncthreads();

    if (t < 12) {
        const float ed = s_ed[t]; const int ei = s_ei[t];
        int r2 = 0;
        #pragma unroll
        for (int o = 0; o < 12; o++)
            r2 += (s_ed[o] < ed) || (s_ed[o] == ed && s_ei[o] < ei);
        if (r2 < KNN) {
            g_knn[(size_t)row * KNN + r2] = ei;
            if (!(row == NB - 1 && r2 == KNN - 1))
                atomicAdd(&g_deg[ei], 1);
        }
    }
}

// ======================================================================
// K5: fused Tx1 gather + both GEMMs + bias (unchanged, verified).
// ======================================================================
__global__ __launch_bounds__(192) void k5_output(const float* __restrict__ W0,
                                                 const float* __restrict__ W1,
                                                 const float* __restrict__ bias,
                                                 float* __restrict__ out) {
    const int node0 = blockIdx.x * 4;
    const int ln = threadIdx.x / 48;
    const int c  = threadIdx.x - ln * 48;
    const int i  = node0 + ln;

    __shared__ float t1[4][48];
    __shared__ int   ssrc[4][KNN];
    __shared__ float sdi[4][KNN];

    if (threadIdx.x < 4 * KNN) {
        const int l = threadIdx.x / KNN, k = threadIdx.x - l * KNN;
        const int e = (node0 + l) * KNN + k;
        const int s = g_knn[e];
        ssrc[l][k] = s;
        float di = 0.f;
        const int dg = g_deg[s];
        if (dg > 0 && e != NB * KNN - 1) di = rsqrtf((float)dg);
        sdi[l][k] = di;
    }
    __syncthreads();

    const float* nodes = (const float*)g_nodes;
    float acc = 0.f;
    #pragma unroll
    for (int k = 0; k < KNN; k++)
        acc += sdi[ln][k] * nodes[(size_t)ssrc[ln][k] * 48 + c];

    const int dgi = g_deg[i];
    const float dinv_i = (dgi > 0) ? rsqrtf((float)dgi) : 0.f;
    t1[ln][c] = -dinv_i * acc;
    __syncthreads();

    float o = bias[c];
    const float* nrow = nodes + (size_t)i * 48;
    #pragma unroll
    for (int cc = 0; cc < 48; cc++)
        o += nrow[cc] * W0[cc * 48 + c] + t1[ln][cc] * W1[cc * 48 + c];
    out[(size_t)i * 48 + c] = o;
}

// ======================================================================
extern "C" void kernel_launch(void* const* d_in, const int* in_sizes, int n_in,
                              void* d_out, int out_size) {
    const float* x    = (const float*)d_in[0];
    const float* W0   = (const float*)d_in[1];
    const float* W1   = (const float*)d_in[2];
    const float* bias = (const float*)d_in[3];
    float* out = (float*)d_out;

    static int configured = 0;
    cudaFuncSetAttribute(k2_knn, cudaFuncAttributeMaxDynamicSharedMemorySize, SMEM_K2);
    (void)configured;

    k1_normalize<<<NB / 128, 128>>>(x);
    k2_knn<<<BATCH * 32, 256, SMEM_K2>>>();
    k3_rerank<<<NB, 64>>>();
    k5_output<<<NB / 4, 192>>>(W0, W1, bias, out);
}